// round 1
// baseline (speedup 1.0000x reference)
#include <cuda_runtime.h>
#include <math.h>

#define BB 512
#define HH 1024
#define SS 1024
#define DD 128
#define KK 32
#define GG 8          // batches per block in kernel A
#define TA 256        // threads in kernel A

// scratch (no allocations allowed)
__device__ float g_gate[BB];
__device__ float g_value[BB * DD];

// shared memory layout (float offsets)
#define OFF_Q      0        // 1024 floats: q[8][128]
#define OFF_LOGIT  1024     // 8192 floats: logits[8][1024]
#define OFF_KEY    9216     // 32768 floats: key tile [1024][32] swizzled (reused: partials/topk/read)
#define OFF_PART   9216     // 8192 floats: per-warp GEMM partials [8w][8g][128]
#define OFF_TOPW   9216     // 256 floats
#define OFF_TOPI   9472     // 256 ints
#define OFF_READ   9728     // 1024 floats
#define OFF_MISC   41984    // 32 floats: per-batch (gate_lat, dmd_lat, phase_lat)
#define SMEM_FLOATS 42016
#define SMEM_BYTES (SMEM_FLOATS * 4)

__global__ void __launch_bounds__(TA, 1)
amt_kernelA(const float* __restrict__ latent,
            const float* __restrict__ memory,
            const float* __restrict__ rqw,  const float* __restrict__ rqb,
            const float* __restrict__ mkey,
            const float* __restrict__ wgw,  const float* __restrict__ wgb,
            const float* __restrict__ dmw,  const float* __restrict__ dmb,
            const float* __restrict__ phw,  const float* __restrict__ phb,
            const float* __restrict__ wvw,  const float* __restrict__ wvb,
            float* __restrict__ out)
{
    extern __shared__ float sm[];
    const int t    = threadIdx.x;
    const int w    = t >> 5;
    const int lane = t & 31;
    const int b0   = blockIdx.x * GG;

    float* out_read = out;                                     // [B][D]
    float* out_wts  = out + (size_t)BB * DD + (size_t)BB * SS * DD;  // [B][S]

    // ---- Phase 0: zero the weights rows owned by this block ----
    {
        float4* p = (float4*)(out_wts + (size_t)b0 * SS);
        #pragma unroll
        for (int i = t; i < GG * SS / 4; i += TA)
            p[i] = make_float4(0.f, 0.f, 0.f, 0.f);
    }

    // ---- Phase 1: latent-side partial dots for gate/dmd/phase (warp g = w) ----
    {
        const int g = w;
        const float* lat = latent + (size_t)(b0 + g) * HH;
        float gl = 0.f, dl = 0.f, pl = 0.f;
        #pragma unroll 4
        for (int j = 0; j < HH / 32; j++) {
            float lv = lat[j * 32 + lane];
            gl += lv * wgw[j * 32 + lane];
            dl += lv * dmw[j * 32 + lane];
            pl += lv * phw[j * 32 + lane];
        }
        #pragma unroll
        for (int o = 16; o > 0; o >>= 1) {
            gl += __shfl_down_sync(0xffffffffu, gl, o);
            dl += __shfl_down_sync(0xffffffffu, dl, o);
            pl += __shfl_down_sync(0xffffffffu, pl, o);
        }
        if (lane == 0) {
            sm[OFF_MISC + g * 4 + 0] = gl;
            sm[OFF_MISC + g * 4 + 1] = dl;
            sm[OFF_MISC + g * 4 + 2] = pl;
        }
    }

    // ---- Load latent register tile: warp w owns h in [w*128, w*128+128) ----
    float latreg[GG][4];
    {
        const int hb = w * 128;
        #pragma unroll
        for (int g = 0; g < GG; g++)
            #pragma unroll
            for (int k = 0; k < 4; k++)
                latreg[g][k] = latent[(size_t)(b0 + g) * HH + hb + k * 32 + lane];
    }

    // ---- Phase 2: query GEMM  q[g][d] = sum_h lat[g][h] * rqw[h][d] + b[d] ----
    {
        const float4* W4 = (const float4*)rqw;
        float4 acc[GG];
        #pragma unroll
        for (int g = 0; g < GG; g++) acc[g] = make_float4(0.f, 0.f, 0.f, 0.f);
        const int hb = w * 128;
        #pragma unroll
        for (int k = 0; k < 4; k++) {
            #pragma unroll 4
            for (int i = 0; i < 32; i++) {
                float4 wv = W4[(hb + k * 32 + i) * 32 + lane];
                #pragma unroll
                for (int g = 0; g < GG; g++) {
                    float a = __shfl_sync(0xffffffffu, latreg[g][k], i);
                    acc[g].x += a * wv.x; acc[g].y += a * wv.y;
                    acc[g].z += a * wv.z; acc[g].w += a * wv.w;
                }
            }
        }
        #pragma unroll
        for (int g = 0; g < GG; g++)
            *(float4*)&sm[OFF_PART + (w * GG + g) * DD + lane * 4] = acc[g];
    }
    __syncthreads();
    {   // reduce partials across warps -> s_q
        const int d  = t & 127;
        const int g0 = t >> 7;
        #pragma unroll
        for (int j = 0; j < 4; j++) {
            int g = g0 + j * 2;
            float s = rqb[d];
            #pragma unroll
            for (int ww = 0; ww < 8; ww++) s += sm[OFF_PART + (ww * GG + g) * DD + d];
            sm[OFF_Q + g * DD + d] = s;
        }
    }
    __syncthreads();

    // ---- Phase 3: value GEMM  v[g][d] = sum_h lat[g][h] * wvw[h][d] + b[d] ----
    {
        const float4* W4 = (const float4*)wvw;
        float4 acc[GG];
        #pragma unroll
        for (int g = 0; g < GG; g++) acc[g] = make_float4(0.f, 0.f, 0.f, 0.f);
        const int hb = w * 128;
        #pragma unroll
        for (int k = 0; k < 4; k++) {
            #pragma unroll 4
            for (int i = 0; i < 32; i++) {
                float4 wv = W4[(hb + k * 32 + i) * 32 + lane];
                #pragma unroll
                for (int g = 0; g < GG; g++) {
                    float a = __shfl_sync(0xffffffffu, latreg[g][k], i);
                    acc[g].x += a * wv.x; acc[g].y += a * wv.y;
                    acc[g].z += a * wv.z; acc[g].w += a * wv.w;
                }
            }
        }
        #pragma unroll
        for (int g = 0; g < GG; g++)
            *(float4*)&sm[OFF_PART + (w * GG + g) * DD + lane * 4] = acc[g];
    }
    __syncthreads();
    {   // reduce partials -> g_value (global scratch)
        const int d  = t & 127;
        const int g0 = t >> 7;
        #pragma unroll
        for (int j = 0; j < 4; j++) {
            int g = g0 + j * 2;
            float s = wvb[d];
            #pragma unroll
            for (int ww = 0; ww < 8; ww++) s += sm[OFF_PART + (ww * GG + g) * DD + d];
            g_value[(size_t)(b0 + g) * DD + d] = s;
        }
    }

    // ---- Phase 4: logits[g][s] = q[g] . mkey[s]  (d-chunked, swizzled smem tile) ----
    float lac[4][GG];
    #pragma unroll
    for (int u = 0; u < 4; u++)
        #pragma unroll
        for (int g = 0; g < GG; g++) lac[u][g] = 0.f;

    const float4* K4 = (const float4*)mkey;
    for (int dc = 0; dc < 4; dc++) {
        __syncthreads();   // also separates previous OFF_PART readers from tile writers
        // stage key tile: [1024 s][32 d] with 16B-unit swizzle j' = j ^ (s&7)
        for (int p = t; p < SS * 8; p += TA) {
            int s = p >> 3;
            int j = p & 7;
            float4 kv = K4[s * 32 + dc * 8 + j];
            int jp = j ^ (s & 7);
            *(float4*)&sm[OFF_KEY + s * 32 + jp * 4] = kv;
        }
        __syncthreads();
        #pragma unroll
        for (int j = 0; j < 8; j++) {
            float4 q4[GG];
            #pragma unroll
            for (int g = 0; g < GG; g++)
                q4[g] = *(const float4*)&sm[OFF_Q + g * DD + dc * 32 + j * 4];
            #pragma unroll
            for (int u = 0; u < 4; u++) {
                int s = w * 128 + u * 32 + lane;
                int jp = j ^ (s & 7);
                float4 k4 = *(const float4*)&sm[OFF_KEY + s * 32 + jp * 4];
                #pragma unroll
                for (int g = 0; g < GG; g++)
                    lac[u][g] += k4.x * q4[g].x + k4.y * q4[g].y
                               + k4.z * q4[g].z + k4.w * q4[g].w;
            }
        }
    }
    // store logits to smem
    #pragma unroll
    for (int u = 0; u < 4; u++) {
        int s = w * 128 + u * 32 + lane;
        #pragma unroll
        for (int g = 0; g < GG; g++)
            sm[OFF_LOGIT + g * SS + s] = lac[u][g];
    }
    __syncthreads();

    // ---- Phase 5: top-32 + renormalized weights (warp g = w) ----
    {
        const int g = w;
        float* lrow = &sm[OFF_LOGIT + g * SS];
        float lmax = -INFINITY; int lidx = 0x7fffffff;
        #pragma unroll 4
        for (int j = 0; j < 32; j++) {
            float v = lrow[j * 32 + lane];
            if (v > lmax) { lmax = v; lidx = j * 32 + lane; }
        }
        float m0 = 0.f, myv = 0.f; int myi = 0;
        for (int k = 0; k < KK; k++) {
            float bv = lmax; int bi = lidx;
            #pragma unroll
            for (int o = 16; o > 0; o >>= 1) {
                float ov = __shfl_down_sync(0xffffffffu, bv, o);
                int   oi = __shfl_down_sync(0xffffffffu, bi, o);
                if (ov > bv || (ov == bv && oi < bi)) { bv = ov; bi = oi; }
            }
            bv = __shfl_sync(0xffffffffu, bv, 0);
            bi = __shfl_sync(0xffffffffu, bi, 0);
            if (k == 0) m0 = bv;
            if (lane == k) { myv = bv; myi = bi; }
            if ((bi & 31) == lane) {   // owner lane: remove & rescan its 32 slots
                lrow[bi] = -INFINITY;
                lmax = -INFINITY; lidx = 0x7fffffff;
                #pragma unroll 4
                for (int j = 0; j < 32; j++) {
                    float v = lrow[j * 32 + lane];
                    if (v > lmax) { lmax = v; lidx = j * 32 + lane; }
                }
            }
        }
        float e = expf(myv - m0);
        float sum = e;
        #pragma unroll
        for (int o = 16; o > 0; o >>= 1) sum += __shfl_xor_sync(0xffffffffu, sum, o);
        float wgt = e / sum;
        sm[OFF_TOPW + g * KK + lane] = wgt;
        ((int*)sm)[OFF_TOPI + g * KK + lane] = myi;
        out_wts[(size_t)(b0 + g) * SS + myi] = wgt;
    }
    __syncthreads();

    // ---- Phase 6: read[g][d] = sum_k w_k * memory[b][idx_k][d] ----
    {
        const int d  = t & 127;
        const int g0 = t >> 7;
        #pragma unroll
        for (int j = 0; j < 4; j++) {
            int g = g0 + j * 2;
            const float* mrow = memory + (size_t)(b0 + g) * SS * DD;
            float accr = 0.f;
            #pragma unroll 4
            for (int k = 0; k < KK; k++) {
                float wk = sm[OFF_TOPW + g * KK + k];
                int   ik = ((int*)sm)[OFF_TOPI + g * KK + k];
                accr += wk * mrow[(size_t)ik * DD + d];
            }
            sm[OFF_READ + g * DD + d] = accr;
            out_read[(size_t)(b0 + g) * DD + d] = accr;
        }
    }
    __syncthreads();

    // ---- Phase 7: gate = f(latent, read); store to scratch ----
    {
        const int g = w;
        float gr = 0.f, dr = 0.f;
        #pragma unroll
        for (int i = 0; i < 4; i++) {
            float rv = sm[OFF_READ + g * DD + lane * 4 + i];
            gr += rv * wgw[HH + lane * 4 + i];
            dr += rv * dmw[HH + lane * 4 + i];
        }
        #pragma unroll
        for (int o = 16; o > 0; o >>= 1) {
            gr += __shfl_down_sync(0xffffffffu, gr, o);
            dr += __shfl_down_sync(0xffffffffu, dr, o);
        }
        if (lane == 0) {
            float gate = 1.f / (1.f + expf(-(sm[OFF_MISC + g * 4 + 0] + gr + wgb[0])));
            float dmd  = tanhf(sm[OFF_MISC + g * 4 + 1] + dr + dmb[0]);
            gate = gate * (0.75f + 0.25f * (dmd + 1.f));
            gate = fminf(fmaxf(gate, 0.f), 1.f);
            float ph = sm[OFF_MISC + g * 4 + 2] + phb[0];
            gate *= 0.5f * (1.f + cosf(ph));
            g_gate[b0 + g] = gate;
        }
    }
}

// ---- Kernel B: new_memory = memory + gw*(value - memory), gw = gate[b]*weights[b][s] ----
__global__ void __launch_bounds__(256)
amt_kernelB(const float* __restrict__ memory, float* __restrict__ out)
{
    const float* wts = out + (size_t)BB * DD + (size_t)BB * SS * DD;
    float* om = out + (size_t)BB * DD;
    const int lane = threadIdx.x & 31;
    const int wrp  = threadIdx.x >> 5;
    const long long row = (long long)blockIdx.x * 8 + wrp;   // row in [0, B*S)
    const int b = (int)(row >> 10);

    float gw = g_gate[b] * wts[row];
    const float4* m4 = (const float4*)memory + row * 32;
    float4* o4 = (float4*)om + row * 32;
    float4 m = m4[lane];
    if (gw != 0.f) {   // warp-uniform branch; 97% of rows skip the value load
        const float4* v4 = (const float4*)g_value + (size_t)b * 32;
        float4 v = v4[lane];
        m.x += gw * (v.x - m.x);
        m.y += gw * (v.y - m.y);
        m.z += gw * (v.z - m.z);
        m.w += gw * (v.w - m.w);
    }
    o4[lane] = m;
}

extern "C" void kernel_launch(void* const* d_in, const int* in_sizes, int n_in,
                              void* d_out, int out_size)
{
    const float* latent = (const float*)d_in[0];
    const float* memory = (const float*)d_in[1];
    const float* rqw    = (const float*)d_in[2];
    const float* rqb    = (const float*)d_in[3];
    const float* mkey   = (const float*)d_in[4];
    const float* wgw    = (const float*)d_in[5];
    const float* wgb    = (const float*)d_in[6];
    const float* dmw    = (const float*)d_in[7];
    const float* dmb    = (const float*)d_in[8];
    const float* phw    = (const float*)d_in[9];
    const float* phb    = (const float*)d_in[10];
    const float* wvw    = (const float*)d_in[11];
    const float* wvb    = (const float*)d_in[12];
    float* out = (float*)d_out;

    cudaFuncSetAttribute(amt_kernelA, cudaFuncAttributeMaxDynamicSharedMemorySize, SMEM_BYTES);

    amt_kernelA<<<BB / GG, TA, SMEM_BYTES>>>(latent, memory, rqw, rqb, mkey,
                                             wgw, wgb, dmw, dmb, phw, phb,
                                             wvw, wvb, out);
    amt_kernelB<<<(BB * SS) / 8, 256>>>(memory, out);
}

// round 2
// speedup vs baseline: 1.5019x; 1.5019x over previous
#include <cuda_runtime.h>
#include <math.h>

#define BB 512
#define HH 1024
#define SS 1024
#define DD 128
#define KK 32
#define GG 4           // batches per A-block
#define TA 256
#define NA (BB / GG)   // 128 A-blocks
#define NC 8192        // copy blocks: NC*256*8 float4 = 256MB
#define NFIX ((BB * KK) / 8)   // fixup blocks (warp per row)

// scratch (no allocations allowed)
__device__ float g_gate[BB];
__device__ float g_value[BB * DD];
__device__ float g_topw[BB * KK];
__device__ int   g_topi[BB * KK];

// shared memory layout (float offsets)
#define OFF_Q      0        // 512:  q[4][128]
#define OFF_LOGIT  512      // 4096: logits[4][1024]
#define OFF_KEY    4608     // 8192: key tile [1024 s][8 d], chunk-swizzled
#define OFF_PART   4608     // 4096: per-warp GEMM partials [8w][4g][128] (aliases KEY)
#define OFF_TOPW   12800    // 128
#define OFF_TOPI   12928    // 128
#define OFF_READ   13056    // 512
#define OFF_MISC   13568    // 32: per-batch per-half (gate,dmd,phase)
#define SMEM_FLOATS 13600
#define SMEM_BYTES (SMEM_FLOATS * 4)

__global__ void __launch_bounds__(TA)
amt_fused(const float* __restrict__ latent,
          const float* __restrict__ memory,
          const float* __restrict__ rqw,  const float* __restrict__ rqb,
          const float* __restrict__ mkey,
          const float* __restrict__ wgw,  const float* __restrict__ wgb,
          const float* __restrict__ dmw,  const float* __restrict__ dmb,
          const float* __restrict__ phw,  const float* __restrict__ phb,
          const float* __restrict__ wvw,  const float* __restrict__ wvb,
          float* __restrict__ out)
{
    extern __shared__ float sm[];
    const int t    = threadIdx.x;
    const int lane = t & 31;

    // ======================= COPY BLOCKS =======================
    if (blockIdx.x >= NA) {
        const int cid = blockIdx.x - NA;
        const size_t base = (size_t)cid * (TA * 8) + t;
        const float4* s4 = (const float4*)memory;
        float4* o4 = (float4*)(out + (size_t)BB * DD);
        float4 v[8];
        #pragma unroll
        for (int k = 0; k < 8; k++) v[k] = __ldcs(&s4[base + k * TA]);
        #pragma unroll
        for (int k = 0; k < 8; k++) __stcs(&o4[base + k * TA], v[k]);
        return;
    }

    // ======================= A BLOCKS =======================
    const int w  = t >> 5;
    const int b0 = blockIdx.x * GG;

    float* out_read = out;                                           // [B][D]
    float* out_wts  = out + (size_t)BB * DD + (size_t)BB * SS * DD;  // [B][S]

    // ---- Phase 0: zero this block's weights rows ----
    {
        float4* p = (float4*)(out_wts + (size_t)b0 * SS);
        #pragma unroll
        for (int i = t; i < GG * SS / 4; i += TA)
            p[i] = make_float4(0.f, 0.f, 0.f, 0.f);
    }

    // ---- Phase 1: latent-side partial dots; warp w: g = w&3, half = w>>2 ----
    {
        const int g = w & 3, half = w >> 2;
        const float* lat = latent + (size_t)(b0 + g) * HH + half * 512;
        const int off = half * 512;
        float gl = 0.f, dl = 0.f, pl = 0.f;
        #pragma unroll 4
        for (int j = 0; j < 16; j++) {
            int h = j * 32 + lane;
            float lv = lat[h];
            gl += lv * wgw[off + h];
            dl += lv * dmw[off + h];
            pl += lv * phw[off + h];
        }
        #pragma unroll
        for (int o = 16; o > 0; o >>= 1) {
            gl += __shfl_down_sync(0xffffffffu, gl, o);
            dl += __shfl_down_sync(0xffffffffu, dl, o);
            pl += __shfl_down_sync(0xffffffffu, pl, o);
        }
        if (lane == 0) {
            sm[OFF_MISC + g * 8 + half * 4 + 0] = gl;
            sm[OFF_MISC + g * 8 + half * 4 + 1] = dl;
            sm[OFF_MISC + g * 8 + half * 4 + 2] = pl;
        }
    }

    // ---- latent register tile: warp w owns h in [w*128, w*128+128) ----
    float latreg[GG][4];
    {
        const int hb = w * 128;
        #pragma unroll
        for (int g = 0; g < GG; g++)
            #pragma unroll
            for (int k = 0; k < 4; k++)
                latreg[g][k] = latent[(size_t)(b0 + g) * HH + hb + k * 32 + lane];
    }

    // ---- Phase 2: query GEMM ----
    {
        const float4* W4 = (const float4*)rqw;
        float4 acc[GG];
        #pragma unroll
        for (int g = 0; g < GG; g++) acc[g] = make_float4(0.f, 0.f, 0.f, 0.f);
        const int hb = w * 128;
        #pragma unroll
        for (int k = 0; k < 4; k++) {
            #pragma unroll 8
            for (int i = 0; i < 32; i++) {
                float4 wv = W4[(hb + k * 32 + i) * 32 + lane];
                #pragma unroll
                for (int g = 0; g < GG; g++) {
                    float a = __shfl_sync(0xffffffffu, latreg[g][k], i);
                    acc[g].x += a * wv.x; acc[g].y += a * wv.y;
                    acc[g].z += a * wv.z; acc[g].w += a * wv.w;
                }
            }
        }
        #pragma unroll
        for (int g = 0; g < GG; g++)
            *(float4*)&sm[OFF_PART + (w * GG + g) * DD + lane * 4] = acc[g];
    }
    __syncthreads();
    {   // reduce partials -> q
        const int d  = t & 127;
        const int g0 = t >> 7;
        #pragma unroll
        for (int j = 0; j < 2; j++) {
            int g = g0 + j * 2;
            float s = rqb[d];
            #pragma unroll
            for (int ww = 0; ww < 8; ww++) s += sm[OFF_PART + (ww * GG + g) * DD + d];
            sm[OFF_Q + g * DD + d] = s;
        }
    }
    __syncthreads();

    // ---- Phase 3: value GEMM ----
    {
        const float4* W4 = (const float4*)wvw;
        float4 acc[GG];
        #pragma unroll
        for (int g = 0; g < GG; g++) acc[g] = make_float4(0.f, 0.f, 0.f, 0.f);
        const int hb = w * 128;
        #pragma unroll
        for (int k = 0; k < 4; k++) {
            #pragma unroll 8
            for (int i = 0; i < 32; i++) {
                float4 wv = W4[(hb + k * 32 + i) * 32 + lane];
                #pragma unroll
                for (int g = 0; g < GG; g++) {
                    float a = __shfl_sync(0xffffffffu, latreg[g][k], i);
                    acc[g].x += a * wv.x; acc[g].y += a * wv.y;
                    acc[g].z += a * wv.z; acc[g].w += a * wv.w;
                }
            }
        }
        #pragma unroll
        for (int g = 0; g < GG; g++)
            *(float4*)&sm[OFF_PART + (w * GG + g) * DD + lane * 4] = acc[g];
    }
    __syncthreads();
    {   // reduce partials -> g_value
        const int d  = t & 127;
        const int g0 = t >> 7;
        #pragma unroll
        for (int j = 0; j < 2; j++) {
            int g = g0 + j * 2;
            float s = wvb[d];
            #pragma unroll
            for (int ww = 0; ww < 8; ww++) s += sm[OFF_PART + (ww * GG + g) * DD + d];
            g_value[(size_t)(b0 + g) * DD + d] = s;
        }
    }

    // ---- Phase 4: logits[g][s] = q[g].mkey[s], 16 chunks of 8 d ----
    float lac[4][GG];
    #pragma unroll
    for (int u = 0; u < 4; u++)
        #pragma unroll
        for (int g = 0; g < GG; g++) lac[u][g] = 0.f;

    const float4* K4 = (const float4*)mkey;
    for (int dc = 0; dc < 16; dc++) {
        __syncthreads();
        // stage 1024 s x 8 d; float4 chunk index c = s*2 + (j ^ ((s>>2)&1))
        #pragma unroll
        for (int p = t; p < SS * 2; p += TA) {
            int s = p >> 1;
            int j = p & 1;
            float4 kv = K4[s * 32 + dc * 2 + j];
            int c = s * 2 + (j ^ ((s >> 2) & 1));
            *(float4*)&sm[OFF_KEY + c * 4] = kv;
        }
        __syncthreads();
        #pragma unroll
        for (int j = 0; j < 2; j++) {
            float4 q4[GG];
            #pragma unroll
            for (int g = 0; g < GG; g++)
                q4[g] = *(const float4*)&sm[OFF_Q + g * DD + dc * 8 + j * 4];
            #pragma unroll
            for (int u = 0; u < 4; u++) {
                int s = w * 128 + u * 32 + lane;
                int c = s * 2 + (j ^ ((s >> 2) & 1));
                float4 k4 = *(const float4*)&sm[OFF_KEY + c * 4];
                #pragma unroll
                for (int g = 0; g < GG; g++)
                    lac[u][g] += k4.x * q4[g].x + k4.y * q4[g].y
                               + k4.z * q4[g].z + k4.w * q4[g].w;
            }
        }
    }
    #pragma unroll
    for (int u = 0; u < 4; u++) {
        int s = w * 128 + u * 32 + lane;
        #pragma unroll
        for (int g = 0; g < GG; g++)
            sm[OFF_LOGIT + g * SS + s] = lac[u][g];
    }
    __syncthreads();

    // ---- Phase 5: top-32 + renormalized weights (warps 0..3, g = w) ----
    if (w < GG) {
        const int g = w;
        float* lrow = &sm[OFF_LOGIT + g * SS];
        float lmax = -INFINITY; int lidx = 0x7fffffff;
        #pragma unroll 4
        for (int j = 0; j < 32; j++) {
            float v = lrow[j * 32 + lane];
            if (v > lmax) { lmax = v; lidx = j * 32 + lane; }
        }
        float m0 = 0.f, myv = 0.f; int myi = 0;
        for (int k = 0; k < KK; k++) {
            float bv = lmax; int bi = lidx;
            #pragma unroll
            for (int o = 16; o > 0; o >>= 1) {
                float ov = __shfl_down_sync(0xffffffffu, bv, o);
                int   oi = __shfl_down_sync(0xffffffffu, bi, o);
                if (ov > bv || (ov == bv && oi < bi)) { bv = ov; bi = oi; }
            }
            bv = __shfl_sync(0xffffffffu, bv, 0);
            bi = __shfl_sync(0xffffffffu, bi, 0);
            if (k == 0) m0 = bv;
            if (lane == k) { myv = bv; myi = bi; }
            if ((bi & 31) == lane) {   // owner lane removes & rescans its column
                lrow[bi] = -INFINITY;
                lmax = -INFINITY; lidx = 0x7fffffff;
                #pragma unroll 4
                for (int j = 0; j < 32; j++) {
                    float v = lrow[j * 32 + lane];
                    if (v > lmax) { lmax = v; lidx = j * 32 + lane; }
                }
            }
        }
        float e = expf(myv - m0);
        float sum = e;
        #pragma unroll
        for (int o = 16; o > 0; o >>= 1) sum += __shfl_xor_sync(0xffffffffu, sum, o);
        float wgt = e / sum;
        sm[OFF_TOPW + g * KK + lane] = wgt;
        ((int*)sm)[OFF_TOPI + g * KK + lane] = myi;
        out_wts[(size_t)(b0 + g) * SS + myi] = wgt;
        g_topw[(size_t)(b0 + g) * KK + lane] = wgt;
        g_topi[(size_t)(b0 + g) * KK + lane] = myi;
    }
    __syncthreads();

    // ---- Phase 6: read[g][d] = sum_k w_k * memory[b][idx_k][d] ----
    {
        const int d  = t & 127;
        const int g0 = t >> 7;
        #pragma unroll
        for (int j = 0; j < 2; j++) {
            int g = g0 + j * 2;
            const float* mrow = memory + (size_t)(b0 + g) * SS * DD;
            float accr = 0.f;
            #pragma unroll 8
            for (int k = 0; k < KK; k++) {
                float wk = sm[OFF_TOPW + g * KK + k];
                int   ik = ((int*)sm)[OFF_TOPI + g * KK + k];
                accr += wk * mrow[(size_t)ik * DD + d];
            }
            sm[OFF_READ + g * DD + d] = accr;
            out_read[(size_t)(b0 + g) * DD + d] = accr;
        }
    }
    __syncthreads();

    // ---- Phase 7: gate (warps 0..3, g = w) ----
    if (w < GG) {
        const int g = w;
        float gr = 0.f, dr = 0.f;
        #pragma unroll
        for (int i = 0; i < 4; i++) {
            float rv = sm[OFF_READ + g * DD + lane * 4 + i];
            gr += rv * wgw[HH + lane * 4 + i];
            dr += rv * dmw[HH + lane * 4 + i];
        }
        #pragma unroll
        for (int o = 16; o > 0; o >>= 1) {
            gr += __shfl_down_sync(0xffffffffu, gr, o);
            dr += __shfl_down_sync(0xffffffffu, dr, o);
        }
        if (lane == 0) {
            float gl = sm[OFF_MISC + g * 8 + 0] + sm[OFF_MISC + g * 8 + 4];
            float dl = sm[OFF_MISC + g * 8 + 1] + sm[OFF_MISC + g * 8 + 5];
            float pl = sm[OFF_MISC + g * 8 + 2] + sm[OFF_MISC + g * 8 + 6];
            float gate = 1.f / (1.f + expf(-(gl + gr + wgb[0])));
            float dmd  = tanhf(dl + dr + dmb[0]);
            gate = gate * (0.75f + 0.25f * (dmd + 1.f));
            gate = fminf(fmaxf(gate, 0.f), 1.f);
            float ph = pl + phb[0];
            gate *= 0.5f * (1.f + cosf(ph));
            g_gate[b0 + g] = gate;
        }
    }
}

// ---- Fixup: rewrite only the topk rows: out = m + gw*(v - m) ----
__global__ void __launch_bounds__(256)
amt_fixup(const float* __restrict__ memory, float* __restrict__ out)
{
    const int lane = threadIdx.x & 31;
    const int wrp  = threadIdx.x >> 5;
    const int W = blockIdx.x * 8 + wrp;          // 0 .. B*K-1
    const int b = W >> 5;
    const int k = W & 31;

    int   idx = g_topi[b * KK + k];
    float gw  = g_gate[b] * g_topw[b * KK + k];

    const size_t row = (size_t)b * SS + idx;
    const float4* m4 = (const float4*)memory + row * 32;
    const float4* v4 = (const float4*)g_value + (size_t)b * 32;
    float4* o4 = (float4*)(out + (size_t)BB * DD) + row * 32;

    float4 m = m4[lane];
    float4 v = v4[lane];
    m.x += gw * (v.x - m.x);
    m.y += gw * (v.y - m.y);
    m.z += gw * (v.z - m.z);
    m.w += gw * (v.w - m.w);
    o4[lane] = m;
}

extern "C" void kernel_launch(void* const* d_in, const int* in_sizes, int n_in,
                              void* d_out, int out_size)
{
    const float* latent = (const float*)d_in[0];
    const float* memory = (const float*)d_in[1];
    const float* rqw    = (const float*)d_in[2];
    const float* rqb    = (const float*)d_in[3];
    const float* mkey   = (const float*)d_in[4];
    const float* wgw    = (const float*)d_in[5];
    const float* wgb    = (const float*)d_in[6];
    const float* dmw    = (const float*)d_in[7];
    const float* dmb    = (const float*)d_in[8];
    const float* phw    = (const float*)d_in[9];
    const float* phb    = (const float*)d_in[10];
    const float* wvw    = (const float*)d_in[11];
    const float* wvb    = (const float*)d_in[12];
    float* out = (float*)d_out;

    cudaFuncSetAttribute(amt_fused, cudaFuncAttributeMaxDynamicSharedMemorySize, SMEM_BYTES);

    amt_fused<<<NA + NC, TA, SMEM_BYTES>>>(latent, memory, rqw, rqb, mkey,
                                           wgw, wgb, dmw, dmb, phw, phb,
                                           wvw, wvb, out);
    amt_fixup<<<NFIX, 256>>>(memory, out);
}